// round 1
// baseline (speedup 1.0000x reference)
#include <cuda_runtime.h>
#include <cstdint>

// ---------------- problem constants ----------------
#define TB    32      // batch rows per CTA
#define NT    256     // threads per CTA
#define CH    64      // K-chunk rows staged in smem
#define DD    128     // module dim
#define APAD  132     // padded row stride for D=128 arrays (bank-conflict free, float4-aligned)
#define OPAD  260     // padded row stride for o (256) tile

// smem layout (floats)
#define XS        (TB*APAD)            // 4224
#define OFF_XIN   0                    // [4][TB][APAD]  (aliases o-tile)
#define OFF_X     (4*XS)               // [4][TB][APAD]
#define OFF_F0    (8*XS)               // [TB][APAD]
#define OFF_G     (9*XS)               // [TB][APAD]
#define OFF_W     (10*XS)              // [CH*DD] = 8192
#define OFF_Z     (OFF_W + CH*DD)      // [TB][12]
#define OFF_LOG   (OFF_Z + TB*12)      // [TB][16]
#define OFF_P     (OFF_LOG + TB*16)    // [TB][16]
#define OFF_PL    (OFF_P + TB*16)      // [TB][4]
#define SMEM_FLOATS (OFF_PL + TB*4)    // 51968
#define SMEM_BYTES  (SMEM_FLOATS*4)    // 207872

// ---------------- packed f32x2 helpers ----------------
__device__ __forceinline__ uint64_t pack2(float lo, float hi) {
    uint64_t r;
    asm("mov.b64 %0, {%1, %2};" : "=l"(r) : "f"(lo), "f"(hi));
    return r;
}
__device__ __forceinline__ void unpack2(uint64_t v, float& lo, float& hi) {
    asm("mov.b64 {%0, %1}, %2;" : "=f"(lo), "=f"(hi) : "l"(v));
}
__device__ __forceinline__ void ffma2(uint64_t& d, uint64_t a, uint64_t b) {
    asm("fma.rn.f32x2 %0, %1, %2, %3;" : "=l"(d) : "l"(a), "l"(b), "l"(d));
}

// ---------------- GEMM: C(32xK @ Kx128) with relu+bias, A in smem, W streamed ----------------
// thread t: rows r0=2*(t>>4), r0+1 ; cols c0=8*(t&15) .. c0+7
__device__ __noinline__ void gemm_tile(
    const float* __restrict__ gW,     // K x 128 row-major, global
    const float* __restrict__ gBias,  // 128
    const float* __restrict__ sA, int lda,
    float*       __restrict__ sOut, int ldo,
    float*       __restrict__ sW,     // CH*128 staging buffer
    int K, bool relu_out)
{
    const int tid = threadIdx.x;
    const int r0 = (tid >> 4) * 2;
    const int c0 = (tid & 15) * 8;
    const int nch = K / CH;

    // prefetch chunk 0 into registers
    float4 reg[8];
    {
        const float4* g4 = (const float4*)gW;
        #pragma unroll
        for (int i = 0; i < 8; ++i) reg[i] = g4[tid + i*NT];
    }

    // accumulators initialized from bias (both rows)
    uint64_t acc[2][4];
    {
        #pragma unroll
        for (int j = 0; j < 4; ++j) {
            acc[0][j] = pack2(gBias[c0 + 2*j], gBias[c0 + 2*j + 1]);
            acc[1][j] = acc[0][j];
        }
    }

    for (int ch = 0; ch < nch; ++ch) {
        // commit prefetched chunk to smem
        {
            float4* sW4 = (float4*)sW;
            #pragma unroll
            for (int i = 0; i < 8; ++i) sW4[tid + i*NT] = reg[i];
        }
        __syncthreads();
        // prefetch next chunk
        if (ch + 1 < nch) {
            const float4* g4 = (const float4*)(gW + (ch + 1)*CH*DD);
            #pragma unroll
            for (int i = 0; i < 8; ++i) reg[i] = g4[tid + i*NT];
        }
        const float* a0 = sA + r0*lda + ch*CH;
        const float* a1 = a0 + lda;
        #pragma unroll
        for (int kk = 0; kk < CH; kk += 4) {
            const float4 av0 = *(const float4*)(a0 + kk);
            const float4 av1 = *(const float4*)(a1 + kk);
            const float a0f[4] = {av0.x, av0.y, av0.z, av0.w};
            const float a1f[4] = {av1.x, av1.y, av1.z, av1.w};
            #pragma unroll
            for (int u = 0; u < 4; ++u) {
                const float* wrow = sW + (kk + u)*DD + c0;
                const ulonglong2 wA = *(const ulonglong2*)(wrow);
                const ulonglong2 wB = *(const ulonglong2*)(wrow + 4);
                const uint64_t p0 = pack2(a0f[u], a0f[u]);
                const uint64_t p1 = pack2(a1f[u], a1f[u]);
                ffma2(acc[0][0], p0, wA.x); ffma2(acc[0][1], p0, wA.y);
                ffma2(acc[0][2], p0, wB.x); ffma2(acc[0][3], p0, wB.y);
                ffma2(acc[1][0], p1, wA.x); ffma2(acc[1][1], p1, wA.y);
                ffma2(acc[1][2], p1, wB.x); ffma2(acc[1][3], p1, wB.y);
            }
        }
        __syncthreads();
    }

    // epilogue: relu + store
    #pragma unroll
    for (int r = 0; r < 2; ++r) {
        float* outp = sOut + (r0 + r)*ldo + c0;
        #pragma unroll
        for (int j = 0; j < 4; ++j) {
            float f0, f1;
            unpack2(acc[r][j], f0, f1);
            if (relu_out) { f0 = fmaxf(f0, 0.f); f1 = fmaxf(f1, 0.f); }
            outp[2*j]     = f0;
            outp[2*j + 1] = f1;
        }
    }
    __syncthreads();
}

extern __shared__ float smem[];

__global__ __launch_bounds__(NT, 1)
void qnet_kernel(
    const float* __restrict__ o, const float* __restrict__ z_map, const float* __restrict__ cp,
    const float* __restrict__ Wb, const float* __restrict__ bb,
    const float* __restrict__ Wz, const float* __restrict__ bz,
    const float* __restrict__ Wm, const float* __restrict__ bm,
    const float* __restrict__ Wg, const float* __restrict__ Wg_last,
    const float* __restrict__ Wv, const float* __restrict__ bv,
    const float* __restrict__ Wa1, const float* __restrict__ ba1,
    const float* __restrict__ Wa2, const float* __restrict__ ba2,
    float* __restrict__ out)
{
    float* sXin = smem + OFF_XIN;   // also o-tile alias
    float* sX   = smem + OFF_X;
    float* sF0  = smem + OFF_F0;
    float* sG   = smem + OFF_G;
    float* sW   = smem + OFF_W;
    float* sZ   = smem + OFF_Z;
    float* sLog = smem + OFF_LOG;
    float* sP   = smem + OFF_P;
    float* sPL  = smem + OFF_PL;
    float* sO   = sXin;             // [TB][OPAD] = 8320 floats < 4*XS

    const int tid  = threadIdx.x;
    const int row0 = blockIdx.x * TB;

    // ---- load o tile (coalesced float4) + z_in (z_map || collision_prob) ----
    {
        const float4* g4 = (const float4*)(o + (size_t)row0 * 256);
        for (int i = tid; i < TB*64; i += NT) {
            int r = i >> 6, c4 = i & 63;
            *(float4*)(sO + r*OPAD + c4*4) = g4[i];
        }
        for (int i = tid; i < TB*10; i += NT) {
            int r = i / 10, c = i - r*10;
            sZ[r*12 + c] = (c < 9) ? z_map[(size_t)(row0 + r)*9 + c] : cp[row0 + r];
        }
    }
    __syncthreads();

    // ---- f0 = relu(o @ Wb + bb) ----
    gemm_tile(Wb, bb, sO, OPAD, sF0, APAD, sW, 256, true);

    // ---- g = relu(z_in @ Wz + bz) * f0 ----
    for (int i = tid; i < 320; i += NT) ((float4*)sW)[i] = ((const float4*)Wz)[i];
    __syncthreads();
    {
        const int r0 = (tid >> 4) * 2;
        const int c0 = (tid & 15) * 8;
        #pragma unroll
        for (int r = 0; r < 2; ++r) {
            float accv[8];
            #pragma unroll
            for (int j = 0; j < 8; ++j) accv[j] = bz[c0 + j];
            #pragma unroll
            for (int k = 0; k < 10; ++k) {
                float a = sZ[(r0 + r)*12 + k];
                #pragma unroll
                for (int j = 0; j < 8; ++j) accv[j] = fmaf(a, sW[k*DD + c0 + j], accv[j]);
            }
            #pragma unroll
            for (int j = 0; j < 8; ++j)
                sG[(r0 + r)*APAD + c0 + j] = fmaxf(accv[j], 0.f) * sF0[(r0 + r)*APAD + c0 + j];
        }
    }
    __syncthreads();

    // ---- layer 0: x[m] = relu(f0 @ Wm[0,m] + bm[0,m]) ----
    for (int m = 0; m < 4; ++m)
        gemm_tile(Wm + (size_t)m*DD*DD, bm + m*DD, sF0, APAD, sX + m*XS, APAD, sW, DD, true);

    // ---- layers 1..3: routing + modules ----
    for (int l = 1; l < 4; ++l) {
        // load Wg[l-1] (128x16)
        {
            const float4* g4 = (const float4*)(Wg + (size_t)(l - 1)*DD*16);
            for (int i = tid; i < 512; i += NT) ((float4*)sW)[i] = g4[i];
        }
        __syncthreads();
        // logits[b][i*4+j] = g[b] . Wg[:, i*4+j]
        for (int idx = tid; idx < TB*16; idx += NT) {
            int b = idx >> 4, ij = idx & 15;
            const float* grow = sG + b*APAD;
            float a = 0.f;
            #pragma unroll 8
            for (int k = 0; k < DD; ++k) a = fmaf(grow[k], sW[k*16 + ij], a);
            sLog[idx] = a;
        }
        __syncthreads();
        // softmax over incoming module i (axis 1)
        if (tid < TB*4) {
            int b = tid >> 2, j = tid & 3;
            float l0 = sLog[b*16 + j],     l1 = sLog[b*16 + 4 + j];
            float l2 = sLog[b*16 + 8 + j], l3 = sLog[b*16 + 12 + j];
            float mx = fmaxf(fmaxf(l0, l1), fmaxf(l2, l3));
            float e0 = expf(l0 - mx), e1 = expf(l1 - mx), e2 = expf(l2 - mx), e3 = expf(l3 - mx);
            float inv = 1.f / (e0 + e1 + e2 + e3);
            sP[b*16 + 0 + j]  = e0*inv;
            sP[b*16 + 4 + j]  = e1*inv;
            sP[b*16 + 8 + j]  = e2*inv;
            sP[b*16 + 12 + j] = e3*inv;
        }
        __syncthreads();
        // xin[j][b][:] = sum_i p[b,i,j] * x[i][b][:]
        for (int idx = tid; idx < TB*DD; idx += NT) {
            int b = idx >> 7, d = idx & 127;
            float x0 = sX[0*XS + b*APAD + d];
            float x1 = sX[1*XS + b*APAD + d];
            float x2 = sX[2*XS + b*APAD + d];
            float x3 = sX[3*XS + b*APAD + d];
            #pragma unroll
            for (int j = 0; j < 4; ++j) {
                float v = sP[b*16 + j]      * x0 + sP[b*16 + 4 + j]  * x1
                        + sP[b*16 + 8 + j]  * x2 + sP[b*16 + 12 + j] * x3;
                sXin[j*XS + b*APAD + d] = v;
            }
        }
        __syncthreads();
        for (int m = 0; m < 4; ++m)
            gemm_tile(Wm + (size_t)(l*4 + m)*DD*DD, bm + (l*4 + m)*DD,
                      sXin + m*XS, APAD, sX + m*XS, APAD, sW, DD, true);
    }

    // ---- p_last + feature ----
    for (int i = tid; i < 128; i += NT) ((float4*)sW)[i] = ((const float4*)Wg_last)[i];
    __syncthreads();
    if (tid < TB*4) {
        int b = tid >> 2, m = tid & 3;
        const float* grow = sG + b*APAD;
        float a = 0.f;
        #pragma unroll 8
        for (int k = 0; k < DD; ++k) a = fmaf(grow[k], sW[k*4 + m], a);
        sLog[b*4 + m] = a;
    }
    __syncthreads();
    if (tid < TB) {
        int b = tid;
        float l0 = sLog[b*4], l1 = sLog[b*4+1], l2 = sLog[b*4+2], l3 = sLog[b*4+3];
        float mx = fmaxf(fmaxf(l0, l1), fmaxf(l2, l3));
        float e0 = expf(l0 - mx), e1 = expf(l1 - mx), e2 = expf(l2 - mx), e3 = expf(l3 - mx);
        float inv = 1.f / (e0 + e1 + e2 + e3);
        sPL[b*4] = e0*inv; sPL[b*4+1] = e1*inv; sPL[b*4+2] = e2*inv; sPL[b*4+3] = e3*inv;
    }
    __syncthreads();
    for (int idx = tid; idx < TB*DD; idx += NT) {
        int b = idx >> 7, d = idx & 127;
        float v = sPL[b*4 + 0] * sX[0*XS + b*APAD + d]
                + sPL[b*4 + 1] * sX[1*XS + b*APAD + d]
                + sPL[b*4 + 2] * sX[2*XS + b*APAD + d]
                + sPL[b*4 + 3] * sX[3*XS + b*APAD + d];
        sF0[b*APAD + d] = v;   // feature reuses sF0
    }
    __syncthreads();

    // ---- a1 = relu(feature @ Wa1 + ba1) -> sG ----
    gemm_tile(Wa1, ba1, sF0, APAD, sG, APAD, sW, DD, true);

    // ---- adv = a1 @ Wa2 + ba2 ----
    for (int i = tid; i < 256; i += NT) ((float4*)sW)[i] = ((const float4*)Wa2)[i];
    __syncthreads();
    {
        int b = tid >> 3, a = tid & 7;
        const float* arow = sG + b*APAD;
        float acc = ba2[a];
        #pragma unroll 8
        for (int k = 0; k < DD; ++k) acc = fmaf(arow[k], sW[k*8 + a], acc);
        sLog[b*8 + a] = acc;
    }
    __syncthreads();

    // ---- value + dueling combine + global store ----
    if (tid < TB) {
        int b = tid;
        float advv[8];
        float s = 0.f;
        #pragma unroll
        for (int a = 0; a < 8; ++a) { advv[a] = sLog[b*8 + a]; s += advv[a]; }
        float mean = s * 0.125f;
        const float* frow = sF0 + b*APAD;
        float v = bv[0];
        #pragma unroll 8
        for (int k = 0; k < DD; ++k) v = fmaf(frow[k], Wv[k], v);
        float* orow = out + (size_t)(row0 + b)*8;
        #pragma unroll
        for (int a = 0; a < 8; ++a) orow[a] = advv[a] - mean + v;
    }
}

extern "C" void kernel_launch(void* const* d_in, const int* in_sizes, int n_in,
                              void* d_out, int out_size) {
    const float* o       = (const float*)d_in[0];
    const float* z_map   = (const float*)d_in[1];
    const float* cp      = (const float*)d_in[2];
    const float* Wb      = (const float*)d_in[3];
    const float* bb      = (const float*)d_in[4];
    const float* Wz      = (const float*)d_in[5];
    const float* bz      = (const float*)d_in[6];
    const float* Wm      = (const float*)d_in[7];
    const float* bm      = (const float*)d_in[8];
    const float* Wg      = (const float*)d_in[9];
    const float* Wg_last = (const float*)d_in[10];
    const float* Wv      = (const float*)d_in[11];
    const float* bv      = (const float*)d_in[12];
    const float* Wa1     = (const float*)d_in[13];
    const float* ba1     = (const float*)d_in[14];
    const float* Wa2     = (const float*)d_in[15];
    const float* ba2     = (const float*)d_in[16];
    float* out = (float*)d_out;

    const int Btot = in_sizes[0] / 256;           // rows of o
    const int grid = (Btot + TB - 1) / TB;

    cudaFuncSetAttribute((const void*)qnet_kernel,
                         cudaFuncAttributeMaxDynamicSharedMemorySize, SMEM_BYTES);

    qnet_kernel<<<grid, NT, SMEM_BYTES>>>(
        o, z_map, cp, Wb, bb, Wz, bz, Wm, bm, Wg, Wg_last,
        Wv, bv, Wa1, ba1, Wa2, ba2, out);
}

// round 2
// speedup vs baseline: 1.0006x; 1.0006x over previous
#include <cuda_runtime.h>
#include <cstdint>

// ---------------- problem constants ----------------
#define TB    32      // batch rows per CTA
#define NT    256     // threads per CTA
#define CH    64      // K-chunk rows staged in smem
#define DD    128     // module dim
#define APAD  132     // padded row stride for D=128 arrays (bank-conflict free, float4-aligned)
#define OPAD  260     // padded row stride for o (256) tile

// smem layout (floats)
#define XS        (TB*APAD)            // 4224
#define OFF_XIN   0                    // [4][TB][APAD]  (aliases o-tile)
#define OFF_X     (4*XS)               // [4][TB][APAD]
#define OFF_F0    (8*XS)               // [TB][APAD]
#define OFF_G     (9*XS)               // [TB][APAD]
#define OFF_W     (10*XS)              // [CH*DD] = 8192
#define OFF_Z     (OFF_W + CH*DD)      // [TB][12]
#define OFF_LOG   (OFF_Z + TB*12)      // [TB][16]
#define OFF_P     (OFF_LOG + TB*16)    // [TB][16]
#define OFF_PL    (OFF_P + TB*16)      // [TB][4]
#define SMEM_FLOATS (OFF_PL + TB*4)    // 51968
#define SMEM_BYTES  (SMEM_FLOATS*4)    // 207872

// ---------------- packed f32x2 helpers ----------------
__device__ __forceinline__ uint64_t pack2(float lo, float hi) {
    uint64_t r;
    asm("mov.b64 %0, {%1, %2};" : "=l"(r) : "f"(lo), "f"(hi));
    return r;
}
__device__ __forceinline__ void unpack2(uint64_t v, float& lo, float& hi) {
    asm("mov.b64 {%0, %1}, %2;" : "=f"(lo), "=f"(hi) : "l"(v));
}
__device__ __forceinline__ void ffma2(uint64_t& d, uint64_t a, uint64_t b) {
    asm("fma.rn.f32x2 %0, %1, %2, %3;" : "=l"(d) : "l"(a), "l"(b), "l"(d));
}

// ---------------- GEMM: C(32xK @ Kx128) with relu+bias, A in smem, W streamed ----------------
// thread t: rows r0=2*(t>>4), r0+1 ; cols c0=8*(t&15) .. c0+7
__device__ __noinline__ void gemm_tile(
    const float* __restrict__ gW,     // K x 128 row-major, global
    const float* __restrict__ gBias,  // 128
    const float* __restrict__ sA, int lda,
    float*       __restrict__ sOut, int ldo,
    float*       __restrict__ sW,     // CH*128 staging buffer
    int K, bool relu_out)
{
    const int tid = threadIdx.x;
    const int r0 = (tid >> 4) * 2;
    const int c0 = (tid & 15) * 8;
    const int nch = K / CH;

    // prefetch chunk 0 into registers
    float4 reg[8];
    {
        const float4* g4 = (const float4*)gW;
        #pragma unroll
        for (int i = 0; i < 8; ++i) reg[i] = g4[tid + i*NT];
    }

    // accumulators initialized from bias (both rows)
    uint64_t acc[2][4];
    {
        #pragma unroll
        for (int j = 0; j < 4; ++j) {
            acc[0][j] = pack2(gBias[c0 + 2*j], gBias[c0 + 2*j + 1]);
            acc[1][j] = acc[0][j];
        }
    }

    for (int ch = 0; ch < nch; ++ch) {
        // commit prefetched chunk to smem
        {
            float4* sW4 = (float4*)sW;
            #pragma unroll
            for (int i = 0; i < 8; ++i) sW4[tid + i*NT] = reg[i];
        }
        __syncthreads();
        // prefetch next chunk
        if (ch + 1 < nch) {
            const float4* g4 = (const float4*)(gW + (ch + 1)*CH*DD);
            #pragma unroll
            for (int i = 0; i < 8; ++i) reg[i] = g4[tid + i*NT];
        }
        const float* a0 = sA + r0*lda + ch*CH;
        const float* a1 = a0 + lda;
        #pragma unroll
        for (int kk = 0; kk < CH; kk += 4) {
            const float4 av0 = *(const float4*)(a0 + kk);
            const float4 av1 = *(const float4*)(a1 + kk);
            const float a0f[4] = {av0.x, av0.y, av0.z, av0.w};
            const float a1f[4] = {av1.x, av1.y, av1.z, av1.w};
            #pragma unroll
            for (int u = 0; u < 4; ++u) {
                const float* wrow = sW + (kk + u)*DD + c0;
                const ulonglong2 wA = *(const ulonglong2*)(wrow);
                const ulonglong2 wB = *(const ulonglong2*)(wrow + 4);
                const uint64_t p0 = pack2(a0f[u], a0f[u]);
                const uint64_t p1 = pack2(a1f[u], a1f[u]);
                ffma2(acc[0][0], p0, wA.x); ffma2(acc[0][1], p0, wA.y);
                ffma2(acc[0][2], p0, wB.x); ffma2(acc[0][3], p0, wB.y);
                ffma2(acc[1][0], p1, wA.x); ffma2(acc[1][1], p1, wA.y);
                ffma2(acc[1][2], p1, wB.x); ffma2(acc[1][3], p1, wB.y);
            }
        }
        __syncthreads();
    }

    // epilogue: relu + store
    #pragma unroll
    for (int r = 0; r < 2; ++r) {
        float* outp = sOut + (r0 + r)*ldo + c0;
        #pragma unroll
        for (int j = 0; j < 4; ++j) {
            float f0, f1;
            unpack2(acc[r][j], f0, f1);
            if (relu_out) { f0 = fmaxf(f0, 0.f); f1 = fmaxf(f1, 0.f); }
            outp[2*j]     = f0;
            outp[2*j + 1] = f1;
        }
    }
    __syncthreads();
}

extern __shared__ float smem[];

__global__ __launch_bounds__(NT, 1)
void qnet_kernel(
    const float* __restrict__ o, const float* __restrict__ z_map, const float* __restrict__ cp,
    const float* __restrict__ Wb, const float* __restrict__ bb,
    const float* __restrict__ Wz, const float* __restrict__ bz,
    const float* __restrict__ Wm, const float* __restrict__ bm,
    const float* __restrict__ Wg, const float* __restrict__ Wg_last,
    const float* __restrict__ Wv, const float* __restrict__ bv,
    const float* __restrict__ Wa1, const float* __restrict__ ba1,
    const float* __restrict__ Wa2, const float* __restrict__ ba2,
    float* __restrict__ out)
{
    float* sXin = smem + OFF_XIN;   // also o-tile alias
    float* sX   = smem + OFF_X;
    float* sF0  = smem + OFF_F0;
    float* sG   = smem + OFF_G;
    float* sW   = smem + OFF_W;
    float* sZ   = smem + OFF_Z;
    float* sLog = smem + OFF_LOG;
    float* sP   = smem + OFF_P;
    float* sPL  = smem + OFF_PL;
    float* sO   = sXin;             // [TB][OPAD] = 8320 floats < 4*XS

    const int tid  = threadIdx.x;
    const int row0 = blockIdx.x * TB;

    // ---- load o tile (coalesced float4) + z_in (z_map || collision_prob) ----
    {
        const float4* g4 = (const float4*)(o + (size_t)row0 * 256);
        for (int i = tid; i < TB*64; i += NT) {
            int r = i >> 6, c4 = i & 63;
            *(float4*)(sO + r*OPAD + c4*4) = g4[i];
        }
        for (int i = tid; i < TB*10; i += NT) {
            int r = i / 10, c = i - r*10;
            sZ[r*12 + c] = (c < 9) ? z_map[(size_t)(row0 + r)*9 + c] : cp[row0 + r];
        }
    }
    __syncthreads();

    // ---- f0 = relu(o @ Wb + bb) ----
    gemm_tile(Wb, bb, sO, OPAD, sF0, APAD, sW, 256, true);

    // ---- g = relu(z_in @ Wz + bz) * f0 ----
    for (int i = tid; i < 320; i += NT) ((float4*)sW)[i] = ((const float4*)Wz)[i];
    __syncthreads();
    {
        const int r0 = (tid >> 4) * 2;
        const int c0 = (tid & 15) * 8;
        #pragma unroll
        for (int r = 0; r < 2; ++r) {
            float accv[8];
            #pragma unroll
            for (int j = 0; j < 8; ++j) accv[j] = bz[c0 + j];
            #pragma unroll
            for (int k = 0; k < 10; ++k) {
                float a = sZ[(r0 + r)*12 + k];
                #pragma unroll
                for (int j = 0; j < 8; ++j) accv[j] = fmaf(a, sW[k*DD + c0 + j], accv[j]);
            }
            #pragma unroll
            for (int j = 0; j < 8; ++j)
                sG[(r0 + r)*APAD + c0 + j] = fmaxf(accv[j], 0.f) * sF0[(r0 + r)*APAD + c0 + j];
        }
    }
    __syncthreads();

    // ---- layer 0: x[m] = relu(f0 @ Wm[0,m] + bm[0,m]) ----
    for (int m = 0; m < 4; ++m)
        gemm_tile(Wm + (size_t)m*DD*DD, bm + m*DD, sF0, APAD, sX + m*XS, APAD, sW, DD, true);

    // ---- layers 1..3: routing + modules ----
    for (int l = 1; l < 4; ++l) {
        // load Wg[l-1] (128x16)
        {
            const float4* g4 = (const float4*)(Wg + (size_t)(l - 1)*DD*16);
            for (int i = tid; i < 512; i += NT) ((float4*)sW)[i] = g4[i];
        }
        __syncthreads();
        // logits[b][i*4+j] = g[b] . Wg[:, i*4+j]
        for (int idx = tid; idx < TB*16; idx += NT) {
            int b = idx >> 4, ij = idx & 15;
            const float* grow = sG + b*APAD;
            float a = 0.f;
            #pragma unroll 8
            for (int k = 0; k < DD; ++k) a = fmaf(grow[k], sW[k*16 + ij], a);
            sLog[idx] = a;
        }
        __syncthreads();
        // softmax over incoming module i (axis 1)
        if (tid < TB*4) {
            int b = tid >> 2, j = tid & 3;
            float l0 = sLog[b*16 + j],     l1 = sLog[b*16 + 4 + j];
            float l2 = sLog[b*16 + 8 + j], l3 = sLog[b*16 + 12 + j];
            float mx = fmaxf(fmaxf(l0, l1), fmaxf(l2, l3));
            float e0 = expf(l0 - mx), e1 = expf(l1 - mx), e2 = expf(l2 - mx), e3 = expf(l3 - mx);
            float inv = 1.f / (e0 + e1 + e2 + e3);
            sP[b*16 + 0 + j]  = e0*inv;
            sP[b*16 + 4 + j]  = e1*inv;
            sP[b*16 + 8 + j]  = e2*inv;
            sP[b*16 + 12 + j] = e3*inv;
        }
        __syncthreads();
        // xin[j][b][:] = sum_i p[b,i,j] * x[i][b][:]
        for (int idx = tid; idx < TB*DD; idx += NT) {
            int b = idx >> 7, d = idx & 127;
            float x0 = sX[0*XS + b*APAD + d];
            float x1 = sX[1*XS + b*APAD + d];
            float x2 = sX[2*XS + b*APAD + d];
            float x3 = sX[3*XS + b*APAD + d];
            #pragma unroll
            for (int j = 0; j < 4; ++j) {
                float v = sP[b*16 + j]      * x0 + sP[b*16 + 4 + j]  * x1
                        + sP[b*16 + 8 + j]  * x2 + sP[b*16 + 12 + j] * x3;
                sXin[j*XS + b*APAD + d] = v;
            }
        }
        __syncthreads();
        for (int m = 0; m < 4; ++m)
            gemm_tile(Wm + (size_t)(l*4 + m)*DD*DD, bm + (l*4 + m)*DD,
                      sXin + m*XS, APAD, sX + m*XS, APAD, sW, DD, true);
    }

    // ---- p_last + feature ----
    for (int i = tid; i < 128; i += NT) ((float4*)sW)[i] = ((const float4*)Wg_last)[i];
    __syncthreads();
    if (tid < TB*4) {
        int b = tid >> 2, m = tid & 3;
        const float* grow = sG + b*APAD;
        float a = 0.f;
        #pragma unroll 8
        for (int k = 0; k < DD; ++k) a = fmaf(grow[k], sW[k*4 + m], a);
        sLog[b*4 + m] = a;
    }
    __syncthreads();
    if (tid < TB) {
        int b = tid;
        float l0 = sLog[b*4], l1 = sLog[b*4+1], l2 = sLog[b*4+2], l3 = sLog[b*4+3];
        float mx = fmaxf(fmaxf(l0, l1), fmaxf(l2, l3));
        float e0 = expf(l0 - mx), e1 = expf(l1 - mx), e2 = expf(l2 - mx), e3 = expf(l3 - mx);
        float inv = 1.f / (e0 + e1 + e2 + e3);
        sPL[b*4] = e0*inv; sPL[b*4+1] = e1*inv; sPL[b*4+2] = e2*inv; sPL[b*4+3] = e3*inv;
    }
    __syncthreads();
    for (int idx = tid; idx < TB*DD; idx += NT) {
        int b = idx >> 7, d = idx & 127;
        float v = sPL[b*4 + 0] * sX[0*XS + b*APAD + d]
                + sPL[b*4 + 1] * sX[1*XS + b*APAD + d]
                + sPL[b*4 + 2] * sX[2*XS + b*APAD + d]
                + sPL[b*4 + 3] * sX[3*XS + b*APAD + d];
        sF0[b*APAD + d] = v;   // feature reuses sF0
    }
    __syncthreads();

    // ---- a1 = relu(feature @ Wa1 + ba1) -> sG ----
    gemm_tile(Wa1, ba1, sF0, APAD, sG, APAD, sW, DD, true);

    // ---- adv = a1 @ Wa2 + ba2 ----
    for (int i = tid; i < 256; i += NT) ((float4*)sW)[i] = ((const float4*)Wa2)[i];
    __syncthreads();
    {
        int b = tid >> 3, a = tid & 7;
        const float* arow = sG + b*APAD;
        float acc = ba2[a];
        #pragma unroll 8
        for (int k = 0; k < DD; ++k) acc = fmaf(arow[k], sW[k*8 + a], acc);
        sLog[b*8 + a] = acc;
    }
    __syncthreads();

    // ---- value + dueling combine + global store ----
    if (tid < TB) {
        int b = tid;
        float advv[8];
        float s = 0.f;
        #pragma unroll
        for (int a = 0; a < 8; ++a) { advv[a] = sLog[b*8 + a]; s += advv[a]; }
        float mean = s * 0.125f;
        const float* frow = sF0 + b*APAD;
        float v = bv[0];
        #pragma unroll 8
        for (int k = 0; k < DD; ++k) v = fmaf(frow[k], Wv[k], v);
        float* orow = out + (size_t)(row0 + b)*8;
        #pragma unroll
        for (int a = 0; a < 8; ++a) orow[a] = advv[a] - mean + v;
    }
}

extern "C" void kernel_launch(void* const* d_in, const int* in_sizes, int n_in,
                              void* d_out, int out_size) {
    const float* o       = (const float*)d_in[0];
    const float* z_map   = (const float*)d_in[1];
    const float* cp      = (const float*)d_in[2];
    const float* Wb      = (const float*)d_in[3];
    const float* bb      = (const float*)d_in[4];
    const float* Wz      = (const float*)d_in[5];
    const float* bz      = (const float*)d_in[6];
    const float* Wm      = (const float*)d_in[7];
    const float* bm      = (const float*)d_in[8];
    const float* Wg      = (const float*)d_in[9];
    const float* Wg_last = (const float*)d_in[10];
    const float* Wv      = (const float*)d_in[11];
    const float* bv      = (const float*)d_in[12];
    const float* Wa1     = (const float*)d_in[13];
    const float* ba1     = (const float*)d_in[14];
    const float* Wa2     = (const float*)d_in[15];
    const float* ba2     = (const float*)d_in[16];
    float* out = (float*)d_out;

    const int Btot = in_sizes[0] / 256;           // rows of o
    const int grid = (Btot + TB - 1) / TB;

    cudaFuncSetAttribute((const void*)qnet_kernel,
                         cudaFuncAttributeMaxDynamicSharedMemorySize, SMEM_BYTES);

    qnet_kernel<<<grid, NT, SMEM_BYTES>>>(
        o, z_map, cp, Wb, bb, Wz, bz, Wm, bm, Wg, Wg_last,
        Wv, bv, Wa1, ba1, Wa2, ba2, out);
}

// round 3
// speedup vs baseline: 2.1779x; 2.1766x over previous
#include <cuda_runtime.h>
#include <cstdint>

// ---------------- problem constants ----------------
#define TB    64      // batch rows per CTA
#define NT    256     // threads per CTA
#define CH    32      // K-chunk rows staged in smem
#define DD    128     // module dim
#define APAD  132     // padded row stride for D=128 activation arrays
#define OPAD  260     // padded row stride for o (256) tile

// smem layout (floats)
#define XS        (TB*APAD)            // 8448
#define OFF_X     0                    // xbuf[4][TB][APAD] (aliases o-tile)
#define OFF_F0    (4*XS)
#define OFF_G     (5*XS)
#define OFF_W     (6*XS)               // [CH*DD] = 4096 (also Wz/Wg/Wg_last/Wa2 staging)
#define OFF_Z     (OFF_W + CH*DD)      // [TB][12]
#define OFF_LOG   (OFF_Z + TB*12)      // [TB][16]
#define OFF_P     (OFF_LOG + TB*16)    // [TB][16]
#define OFF_PL    (OFF_P + TB*16)      // [TB][4]
#define SMEM_FLOATS (OFF_PL + TB*4)    // 57856
#define SMEM_BYTES  (SMEM_FLOATS*4)    // 231424

// ---------------- packed f32x2 helpers ----------------
__device__ __forceinline__ uint64_t pack2(float lo, float hi) {
    uint64_t r;
    asm("mov.b64 %0, {%1, %2};" : "=l"(r) : "f"(lo), "f"(hi));
    return r;
}
__device__ __forceinline__ void unpack2(uint64_t v, float& lo, float& hi) {
    asm("mov.b64 {%0, %1}, %2;" : "=f"(lo), "=f"(hi) : "l"(v));
}
__device__ __forceinline__ void ffma2(uint64_t& d, uint64_t a, uint64_t b) {
    asm("fma.rn.f32x2 %0, %1, %2, %3;" : "=l"(d) : "l"(a), "l"(b), "l"(d));
}

// ---------------- GEMM: C(64 x K @ K x 128) + bias + relu ----------------
// thread t: rows r0=4*(t>>4)..+3 ; cols {c4..c4+3, 64+c4..64+c4+3}, c4=4*(t&15)
// W LDS: 16 lanes x 16B contiguous -> conflict-free. In-place safe (sOut may == sA).
__device__ __noinline__ void gemm_tile(
    const float* __restrict__ gW,     // K x 128 row-major, global
    const float* __restrict__ gBias,  // 128
    float* __restrict__ sA, int lda,
    float* __restrict__ sOut, int ldo,
    float* __restrict__ sW,           // CH*128 staging buffer
    int K)
{
    const int tid = threadIdx.x;
    const int r0 = (tid >> 4) * 4;
    const int c4 = (tid & 15) * 4;
    const int nch = K / CH;

    // prefetch chunk 0 into registers
    float4 reg[4];
    {
        const float4* g4 = (const float4*)gW;
        #pragma unroll
        for (int i = 0; i < 4; ++i) reg[i] = g4[tid + i*NT];
    }

    // accumulators initialized from bias
    uint64_t acc[4][4];
    {
        uint64_t b0 = pack2(gBias[c4 + 0], gBias[c4 + 1]);
        uint64_t b1 = pack2(gBias[c4 + 2], gBias[c4 + 3]);
        uint64_t b2 = pack2(gBias[64 + c4 + 0], gBias[64 + c4 + 1]);
        uint64_t b3 = pack2(gBias[64 + c4 + 2], gBias[64 + c4 + 3]);
        #pragma unroll
        for (int r = 0; r < 4; ++r) {
            acc[r][0] = b0; acc[r][1] = b1; acc[r][2] = b2; acc[r][3] = b3;
        }
    }

    for (int ch = 0; ch < nch; ++ch) {
        {
            float4* sW4 = (float4*)sW;
            #pragma unroll
            for (int i = 0; i < 4; ++i) sW4[tid + i*NT] = reg[i];
        }
        __syncthreads();
        if (ch + 1 < nch) {
            const float4* g4 = (const float4*)(gW + (size_t)(ch + 1)*CH*DD);
            #pragma unroll
            for (int i = 0; i < 4; ++i) reg[i] = g4[tid + i*NT];
        }
        const float* aBase = sA + r0*lda + ch*CH;
        for (int kk = 0; kk < CH; kk += 4) {
            float a[4][4];
            #pragma unroll
            for (int r = 0; r < 4; ++r) {
                const float4 av = *(const float4*)(aBase + r*lda + kk);
                a[r][0] = av.x; a[r][1] = av.y; a[r][2] = av.z; a[r][3] = av.w;
            }
            #pragma unroll
            for (int u = 0; u < 4; ++u) {
                const float* wrow = sW + (kk + u)*DD;
                const ulonglong2 wA = *(const ulonglong2*)(wrow + c4);        // conflict-free
                const ulonglong2 wB = *(const ulonglong2*)(wrow + 64 + c4);   // conflict-free
                #pragma unroll
                for (int r = 0; r < 4; ++r) {
                    const uint64_t p = pack2(a[r][u], a[r][u]);
                    ffma2(acc[r][0], p, wA.x); ffma2(acc[r][1], p, wA.y);
                    ffma2(acc[r][2], p, wB.x); ffma2(acc[r][3], p, wB.y);
                }
            }
        }
        __syncthreads();
    }

    // epilogue: relu + store (after final sync -> in-place safe)
    #pragma unroll
    for (int r = 0; r < 4; ++r) {
        float* outp = sOut + (r0 + r)*ldo;
        float f0, f1, f2, f3;
        unpack2(acc[r][0], f0, f1); unpack2(acc[r][1], f2, f3);
        float4 v0 = {fmaxf(f0,0.f), fmaxf(f1,0.f), fmaxf(f2,0.f), fmaxf(f3,0.f)};
        *(float4*)(outp + c4) = v0;
        unpack2(acc[r][2], f0, f1); unpack2(acc[r][3], f2, f3);
        float4 v1 = {fmaxf(f0,0.f), fmaxf(f1,0.f), fmaxf(f2,0.f), fmaxf(f3,0.f)};
        *(float4*)(outp + 64 + c4) = v1;
    }
    __syncthreads();
}

extern __shared__ float smem[];

__global__ __launch_bounds__(NT, 1)
void qnet_kernel(
    const float* __restrict__ o, const float* __restrict__ z_map, const float* __restrict__ cp,
    const float* __restrict__ Wb, const float* __restrict__ bb,
    const float* __restrict__ Wz, const float* __restrict__ bz,
    const float* __restrict__ Wm, const float* __restrict__ bm,
    const float* __restrict__ Wg, const float* __restrict__ Wg_last,
    const float* __restrict__ Wv, const float* __restrict__ bv,
    const float* __restrict__ Wa1, const float* __restrict__ ba1,
    const float* __restrict__ Wa2, const float* __restrict__ ba2,
    float* __restrict__ out)
{
    float* sX   = smem + OFF_X;     // xbuf[4]
    float* sF0  = smem + OFF_F0;
    float* sG   = smem + OFF_G;
    float* sW   = smem + OFF_W;
    float* sZ   = smem + OFF_Z;
    float* sLog = smem + OFF_LOG;
    float* sP   = smem + OFF_P;
    float* sPL  = smem + OFF_PL;
    float* sO   = sX;               // o-tile aliases xbuf[0..1]: 64*260=16640 < 2*XS

    const int tid  = threadIdx.x;
    const int row0 = blockIdx.x * TB;

    // ---- load o tile + z_in ----
    {
        const float4* g4 = (const float4*)(o + (size_t)row0 * 256);
        for (int i = tid; i < TB*64; i += NT) {
            int r = i >> 6, c = i & 63;
            *(float4*)(sO + r*OPAD + c*4) = g4[i];
        }
        for (int i = tid; i < TB*10; i += NT) {
            int r = i / 10, c = i - r*10;
            sZ[r*12 + c] = (c < 9) ? z_map[(size_t)(row0 + r)*9 + c] : cp[row0 + r];
        }
    }
    __syncthreads();

    // ---- f0 = relu(o @ Wb + bb) ----
    gemm_tile(Wb, bb, sO, OPAD, sF0, APAD, sW, 256);

    // ---- g = relu(z_in @ Wz + bz) * f0 ----
    for (int i = tid; i < 320; i += NT) ((float4*)sW)[i] = ((const float4*)Wz)[i];
    __syncthreads();
    for (int idx = tid; idx < TB*DD; idx += NT) {
        int b = idx >> 7, c = idx & 127;
        float a = bz[c];
        #pragma unroll
        for (int k = 0; k < 10; ++k) a = fmaf(sZ[b*12 + k], sW[k*DD + c], a);
        sG[b*APAD + c] = fmaxf(a, 0.f) * sF0[b*APAD + c];
    }
    __syncthreads();

    // ---- layer 0 ----
    for (int m = 0; m < 4; ++m)
        gemm_tile(Wm + (size_t)m*DD*DD, bm + m*DD, sF0, APAD, sX + m*XS, APAD, sW, DD);

    // ---- layers 1..3 ----
    for (int l = 1; l < 4; ++l) {
        {
            const float4* g4 = (const float4*)(Wg + (size_t)(l - 1)*DD*16);
            for (int i = tid; i < 512; i += NT) ((float4*)sW)[i] = g4[i];
        }
        __syncthreads();
        for (int idx = tid; idx < TB*16; idx += NT) {
            int b = idx >> 4, ij = idx & 15;
            const float* grow = sG + b*APAD;
            float a = 0.f;
            #pragma unroll 8
            for (int k = 0; k < DD; ++k) a = fmaf(grow[k], sW[k*16 + ij], a);
            sLog[idx] = a;
        }
        __syncthreads();
        // softmax over incoming i (axis 1); NT == TB*4
        {
            int b = tid >> 2, j = tid & 3;
            float l0 = sLog[b*16 + j],     l1 = sLog[b*16 + 4 + j];
            float l2 = sLog[b*16 + 8 + j], l3 = sLog[b*16 + 12 + j];
            float mx = fmaxf(fmaxf(l0, l1), fmaxf(l2, l3));
            float e0 = expf(l0 - mx), e1 = expf(l1 - mx), e2 = expf(l2 - mx), e3 = expf(l3 - mx);
            float inv = 1.f / (e0 + e1 + e2 + e3);
            sP[b*16 + 0 + j]  = e0*inv;
            sP[b*16 + 4 + j]  = e1*inv;
            sP[b*16 + 8 + j]  = e2*inv;
            sP[b*16 + 12 + j] = e3*inv;
        }
        __syncthreads();
        // in-place mix: xin[j] = sum_i p[b,i,j] * x[i]
        for (int idx = tid; idx < TB*DD; idx += NT) {
            int b = idx >> 7, d = idx & 127;
            float x0 = sX[0*XS + b*APAD + d];
            float x1 = sX[1*XS + b*APAD + d];
            float x2 = sX[2*XS + b*APAD + d];
            float x3 = sX[3*XS + b*APAD + d];
            #pragma unroll
            for (int j = 0; j < 4; ++j) {
                float v = sP[b*16 + j]      * x0 + sP[b*16 + 4 + j]  * x1
                        + sP[b*16 + 8 + j]  * x2 + sP[b*16 + 12 + j] * x3;
                sX[j*XS + b*APAD + d] = v;
            }
        }
        __syncthreads();
        for (int m = 0; m < 4; ++m)
            gemm_tile(Wm + (size_t)(l*4 + m)*DD*DD, bm + (l*4 + m)*DD,
                      sX + m*XS, APAD, sX + m*XS, APAD, sW, DD);   // in-place
    }

    // ---- p_last (must precede sG overwrite) ----
    for (int i = tid; i < 128; i += NT) ((float4*)sW)[i] = ((const float4*)Wg_last)[i];
    __syncthreads();
    {
        int b = tid >> 2, m = tid & 3;    // NT == TB*4
        const float* grow = sG + b*APAD;
        float a = 0.f;
        #pragma unroll 8
        for (int k = 0; k < DD; ++k) a = fmaf(grow[k], sW[k*4 + m], a);
        sLog[b*4 + m] = a;
    }
    __syncthreads();
    if (tid < TB) {
        int b = tid;
        float l0 = sLog[b*4], l1 = sLog[b*4+1], l2 = sLog[b*4+2], l3 = sLog[b*4+3];
        float mx = fmaxf(fmaxf(l0, l1), fmaxf(l2, l3));
        float e0 = expf(l0 - mx), e1 = expf(l1 - mx), e2 = expf(l2 - mx), e3 = expf(l3 - mx);
        float inv = 1.f / (e0 + e1 + e2 + e3);
        sPL[b*4] = e0*inv; sPL[b*4+1] = e1*inv; sPL[b*4+2] = e2*inv; sPL[b*4+3] = e3*inv;
    }
    __syncthreads();

    // ---- feature = sum_m p_last[m] * x[m] -> sF0 ----
    for (int idx = tid; idx < TB*DD; idx += NT) {
        int b = idx >> 7, d = idx & 127;
        float v = sPL[b*4 + 0] * sX[0*XS + b*APAD + d]
                + sPL[b*4 + 1] * sX[1*XS + b*APAD + d]
                + sPL[b*4 + 2] * sX[2*XS + b*APAD + d]
                + sPL[b*4 + 3] * sX[3*XS + b*APAD + d];
        sF0[b*APAD + d] = v;
    }
    __syncthreads();

    // ---- a1 = relu(feature @ Wa1 + ba1) -> sG (G dead now) ----
    gemm_tile(Wa1, ba1, sF0, APAD, sG, APAD, sW, DD);

    // ---- adv = a1 @ Wa2 + ba2 ----
    for (int i = tid; i < 256; i += NT) ((float4*)sW)[i] = ((const float4*)Wa2)[i];
    __syncthreads();
    for (int idx = tid; idx < TB*8; idx += NT) {
        int b = idx >> 3, a = idx & 7;
        const float* arow = sG + b*APAD;
        float acc = ba2[a];
        #pragma unroll 8
        for (int k = 0; k < DD; ++k) acc = fmaf(arow[k], sW[k*8 + a], acc);
        sLog[b*8 + a] = acc;
    }
    __syncthreads();

    // ---- value + dueling combine + store ----
    if (tid < TB) {
        int b = tid;
        float advv[8];
        float s = 0.f;
        #pragma unroll
        for (int a = 0; a < 8; ++a) { advv[a] = sLog[b*8 + a]; s += advv[a]; }
        float mean = s * 0.125f;
        const float* frow = sF0 + b*APAD;
        float v = bv[0];
        #pragma unroll 8
        for (int k = 0; k < DD; ++k) v = fmaf(frow[k], Wv[k], v);
        float* orow = out + (size_t)(row0 + b)*8;
        #pragma unroll
        for (int a = 0; a < 8; ++a) orow[a] = advv[a] - mean + v;
    }
}

extern "C" void kernel_launch(void* const* d_in, const int* in_sizes, int n_in,
                              void* d_out, int out_size) {
    const float* o       = (const float*)d_in[0];
    const float* z_map   = (const float*)d_in[1];
    const float* cp      = (const float*)d_in[2];
    const float* Wb      = (const float*)d_in[3];
    const float* bb      = (const float*)d_in[4];
    const float* Wz      = (const float*)d_in[5];
    const float* bz      = (const float*)d_in[6];
    const float* Wm      = (const float*)d_in[7];
    const float* bm      = (const float*)d_in[8];
    const float* Wg      = (const float*)d_in[9];
    const float* Wg_last = (const float*)d_in[10];
    const float* Wv      = (const float*)d_in[11];
    const float* bv      = (const float*)d_in[12];
    const float* Wa1     = (const float*)d_in[13];
    const float* ba1     = (const float*)d_in[14];
    const float* Wa2     = (const float*)d_in[15];
    const float* ba2     = (const float*)d_in[16];
    float* out = (float*)d_out;

    const int Btot = in_sizes[0] / 256;
    const int grid = (Btot + TB - 1) / TB;

    cudaFuncSetAttribute((const void*)qnet_kernel,
                         cudaFuncAttributeMaxDynamicSharedMemorySize, SMEM_BYTES);

    qnet_kernel<<<grid, NT, SMEM_BYTES>>>(
        o, z_map, cp, Wb, bb, Wz, bz, Wm, bm, Wg, Wg_last,
        Wv, bv, Wa1, ba1, Wa2, ba2, out);
}

// round 4
// speedup vs baseline: 2.5195x; 1.1568x over previous
#include <cuda_runtime.h>
#include <cstdint>

// ---------------- problem constants ----------------
#define TB    64      // batch rows per CTA
#define NT    256     // threads per CTA (8 warps)
#define CH    32      // K-chunk rows staged in smem
#define DD    128     // module dim
#define APAD  132     // padded row stride for D=128 activation arrays
#define OPAD  260     // padded row stride for o (256) tile

// smem layout (floats)
#define XS        (TB*APAD)            // 8448
#define OFF_X     0                    // xbuf[4][TB][APAD] (aliases o-tile)
#define OFF_F0    (4*XS)
#define OFF_G     (5*XS)
#define OFF_W     (6*XS)               // [CH*DD] = 4096 (also Wz/Wg/Wg_last/Wa2 staging)
#define OFF_Z     (OFF_W + CH*DD)      // [TB][12]
#define OFF_LOG   (OFF_Z + TB*12)      // [TB][16]
#define OFF_P     (OFF_LOG + TB*16)    // [TB][16]
#define OFF_PL    (OFF_P + TB*16)      // [TB][4]
#define SMEM_FLOATS (OFF_PL + TB*4)    // 57856
#define SMEM_BYTES  (SMEM_FLOATS*4)    // 231424

// ---------------- packed f32x2 helpers ----------------
__device__ __forceinline__ uint64_t pack2(float lo, float hi) {
    uint64_t r;
    asm("mov.b64 %0, {%1, %2};" : "=l"(r) : "f"(lo), "f"(hi));
    return r;
}
__device__ __forceinline__ void unpack2(uint64_t v, float& lo, float& hi) {
    asm("mov.b64 {%0, %1}, %2;" : "=f"(lo), "=f"(hi) : "l"(v));
}
__device__ __forceinline__ void ffma2(uint64_t& d, uint64_t a, uint64_t b) {
    asm("fma.rn.f32x2 %0, %1, %2, %3;" : "=l"(d) : "l"(a), "l"(b), "l"(d));
}

// ---------------- GEMM: C(64 x K @ K x 128) + bias + relu ----------------
// Broadcast-W mapping:
//   warp w (0..7) owns cols [16w, 16w+16)  -> W reads are warp-broadcast (N=1)
//   lane l owns rows {l, l+32}             -> A reads conflict-free (stride 132 fl)
// In-place safe (sOut may == sA): all A reads precede the final chunk sync.
__device__ __noinline__ void gemm_tile(
    const float* __restrict__ gW,     // K x 128 row-major, global
    const float* __restrict__ gBias,  // 128
    float* __restrict__ sA, int lda,
    float* __restrict__ sOut, int ldo,
    float* __restrict__ sW,           // CH*128 staging buffer
    int K)
{
    const int tid  = threadIdx.x;
    const int lane = tid & 31;
    const int c0   = (tid >> 5) * 16;   // warp's column base
    const int nch  = K / CH;

    // prefetch chunk 0 into registers
    float4 reg[4];
    {
        const float4* g4 = (const float4*)gW;
        #pragma unroll
        for (int i = 0; i < 4; ++i) reg[i] = g4[tid + i*NT];
    }

    // accumulators: 2 rows x 16 cols, initialized from bias
    uint64_t acc[2][8];
    #pragma unroll
    for (int j = 0; j < 8; ++j) {
        acc[0][j] = pack2(gBias[c0 + 2*j], gBias[c0 + 2*j + 1]);
        acc[1][j] = acc[0][j];
    }

    for (int ch = 0; ch < nch; ++ch) {
        {
            float4* sW4 = (float4*)sW;
            #pragma unroll
            for (int i = 0; i < 4; ++i) sW4[tid + i*NT] = reg[i];
        }
        __syncthreads();
        if (ch + 1 < nch) {
            const float4* g4 = (const float4*)(gW + (size_t)(ch + 1)*CH*DD);
            #pragma unroll
            for (int i = 0; i < 4; ++i) reg[i] = g4[tid + i*NT];
        }
        const float* a0p = sA + lane*lda + ch*CH;
        const float* a1p = a0p + 32*lda;
        #pragma unroll
        for (int kk = 0; kk < CH; kk += 4) {
            const float4 av0 = *(const float4*)(a0p + kk);
            const float4 av1 = *(const float4*)(a1p + kk);
            const float a0f[4] = {av0.x, av0.y, av0.z, av0.w};
            const float a1f[4] = {av1.x, av1.y, av1.z, av1.w};
            #pragma unroll
            for (int u = 0; u < 4; ++u) {
                const float* wrow = sW + (kk + u)*DD + c0;  // broadcast across lanes
                const ulonglong2 w0 = *(const ulonglong2*)(wrow);
                const ulonglong2 w1 = *(const ulonglong2*)(wrow + 4);
                const ulonglong2 w2 = *(const ulonglong2*)(wrow + 8);
                const ulonglong2 w3 = *(const ulonglong2*)(wrow + 12);
                const uint64_t p0 = pack2(a0f[u], a0f[u]);
                const uint64_t p1 = pack2(a1f[u], a1f[u]);
                ffma2(acc[0][0], p0, w0.x); ffma2(acc[0][1], p0, w0.y);
                ffma2(acc[0][2], p0, w1.x); ffma2(acc[0][3], p0, w1.y);
                ffma2(acc[0][4], p0, w2.x); ffma2(acc[0][5], p0, w2.y);
                ffma2(acc[0][6], p0, w3.x); ffma2(acc[0][7], p0, w3.y);
                ffma2(acc[1][0], p1, w0.x); ffma2(acc[1][1], p1, w0.y);
                ffma2(acc[1][2], p1, w1.x); ffma2(acc[1][3], p1, w1.y);
                ffma2(acc[1][4], p1, w2.x); ffma2(acc[1][5], p1, w2.y);
                ffma2(acc[1][6], p1, w3.x); ffma2(acc[1][7], p1, w3.y);
            }
        }
        __syncthreads();
    }

    // epilogue: relu + store (after final sync -> in-place safe)
    #pragma unroll
    for (int r = 0; r < 2; ++r) {
        float* outp = sOut + (lane + r*32)*ldo + c0;
        #pragma unroll
        for (int q = 0; q < 2; ++q) {
            float f0, f1, f2, f3;
            unpack2(acc[r][4*q + 0], f0, f1); unpack2(acc[r][4*q + 1], f2, f3);
            float4 v0 = {fmaxf(f0,0.f), fmaxf(f1,0.f), fmaxf(f2,0.f), fmaxf(f3,0.f)};
            *(float4*)(outp + 8*q) = v0;
            unpack2(acc[r][4*q + 2], f0, f1); unpack2(acc[r][4*q + 3], f2, f3);
            float4 v1 = {fmaxf(f0,0.f), fmaxf(f1,0.f), fmaxf(f2,0.f), fmaxf(f3,0.f)};
            *(float4*)(outp + 8*q + 4) = v1;
        }
    }
    __syncthreads();
}

extern __shared__ float smem[];

__global__ __launch_bounds__(NT, 1)
void qnet_kernel(
    const float* __restrict__ o, const float* __restrict__ z_map, const float* __restrict__ cp,
    const float* __restrict__ Wb, const float* __restrict__ bb,
    const float* __restrict__ Wz, const float* __restrict__ bz,
    const float* __restrict__ Wm, const float* __restrict__ bm,
    const float* __restrict__ Wg, const float* __restrict__ Wg_last,
    const float* __restrict__ Wv, const float* __restrict__ bv,
    const float* __restrict__ Wa1, const float* __restrict__ ba1,
    const float* __restrict__ Wa2, const float* __restrict__ ba2,
    float* __restrict__ out)
{
    float* sX   = smem + OFF_X;     // xbuf[4]
    float* sF0  = smem + OFF_F0;
    float* sG   = smem + OFF_G;
    float* sW   = smem + OFF_W;
    float* sZ   = smem + OFF_Z;
    float* sLog = smem + OFF_LOG;
    float* sP   = smem + OFF_P;
    float* sPL  = smem + OFF_PL;
    float* sO   = sX;               // o-tile aliases xbuf[0..1]: 64*260=16640 < 2*XS

    const int tid  = threadIdx.x;
    const int row0 = blockIdx.x * TB;

    // ---- load o tile + z_in ----
    {
        const float4* g4 = (const float4*)(o + (size_t)row0 * 256);
        for (int i = tid; i < TB*64; i += NT) {
            int r = i >> 6, c = i & 63;
            *(float4*)(sO + r*OPAD + c*4) = g4[i];
        }
        for (int i = tid; i < TB*10; i += NT) {
            int r = i / 10, c = i - r*10;
            sZ[r*12 + c] = (c < 9) ? z_map[(size_t)(row0 + r)*9 + c] : cp[row0 + r];
        }
    }
    __syncthreads();

    // ---- f0 = relu(o @ Wb + bb) ----
    gemm_tile(Wb, bb, sO, OPAD, sF0, APAD, sW, 256);

    // ---- g = relu(z_in @ Wz + bz) * f0 ----
    for (int i = tid; i < 320; i += NT) ((float4*)sW)[i] = ((const float4*)Wz)[i];
    __syncthreads();
    for (int idx = tid; idx < TB*DD; idx += NT) {
        int b = idx >> 7, c = idx & 127;
        float a = bz[c];
        #pragma unroll
        for (int k = 0; k < 10; ++k) a = fmaf(sZ[b*12 + k], sW[k*DD + c], a);
        sG[b*APAD + c] = fmaxf(a, 0.f) * sF0[b*APAD + c];
    }
    __syncthreads();

    // ---- layer 0 ----
    for (int m = 0; m < 4; ++m)
        gemm_tile(Wm + (size_t)m*DD*DD, bm + m*DD, sF0, APAD, sX + m*XS, APAD, sW, DD);

    // ---- layers 1..3 ----
    for (int l = 1; l < 4; ++l) {
        {
            const float4* g4 = (const float4*)(Wg + (size_t)(l - 1)*DD*16);
            for (int i = tid; i < 512; i += NT) ((float4*)sW)[i] = g4[i];
        }
        __syncthreads();
        for (int idx = tid; idx < TB*16; idx += NT) {
            int b = idx >> 4, ij = idx & 15;
            const float* grow = sG + b*APAD;
            float a = 0.f;
            #pragma unroll 8
            for (int k = 0; k < DD; ++k) a = fmaf(grow[k], sW[k*16 + ij], a);
            sLog[idx] = a;
        }
        __syncthreads();
        // softmax over incoming i (axis 1); NT == TB*4
        {
            int b = tid >> 2, j = tid & 3;
            float l0 = sLog[b*16 + j],     l1 = sLog[b*16 + 4 + j];
            float l2 = sLog[b*16 + 8 + j], l3 = sLog[b*16 + 12 + j];
            float mx = fmaxf(fmaxf(l0, l1), fmaxf(l2, l3));
            float e0 = expf(l0 - mx), e1 = expf(l1 - mx), e2 = expf(l2 - mx), e3 = expf(l3 - mx);
            float inv = 1.f / (e0 + e1 + e2 + e3);
            sP[b*16 + 0 + j]  = e0*inv;
            sP[b*16 + 4 + j]  = e1*inv;
            sP[b*16 + 8 + j]  = e2*inv;
            sP[b*16 + 12 + j] = e3*inv;
        }
        __syncthreads();
        // in-place mix: xin[j] = sum_i p[b,i,j] * x[i]
        for (int idx = tid; idx < TB*DD; idx += NT) {
            int b = idx >> 7, d = idx & 127;
            float x0 = sX[0*XS + b*APAD + d];
            float x1 = sX[1*XS + b*APAD + d];
            float x2 = sX[2*XS + b*APAD + d];
            float x3 = sX[3*XS + b*APAD + d];
            #pragma unroll
            for (int j = 0; j < 4; ++j) {
                float v = sP[b*16 + j]      * x0 + sP[b*16 + 4 + j]  * x1
                        + sP[b*16 + 8 + j]  * x2 + sP[b*16 + 12 + j] * x3;
                sX[j*XS + b*APAD + d] = v;
            }
        }
        __syncthreads();
        for (int m = 0; m < 4; ++m)
            gemm_tile(Wm + (size_t)(l*4 + m)*DD*DD, bm + (l*4 + m)*DD,
                      sX + m*XS, APAD, sX + m*XS, APAD, sW, DD);   // in-place
    }

    // ---- p_last (must precede sG overwrite) ----
    for (int i = tid; i < 128; i += NT) ((float4*)sW)[i] = ((const float4*)Wg_last)[i];
    __syncthreads();
    {
        int b = tid >> 2, m = tid & 3;    // NT == TB*4
        const float* grow = sG + b*APAD;
        float a = 0.f;
        #pragma unroll 8
        for (int k = 0; k < DD; ++k) a = fmaf(grow[k], sW[k*4 + m], a);
        sLog[b*4 + m] = a;
    }
    __syncthreads();
    if (tid < TB) {
        int b = tid;
        float l0 = sLog[b*4], l1 = sLog[b*4+1], l2 = sLog[b*4+2], l3 = sLog[b*4+3];
        float mx = fmaxf(fmaxf(l0, l1), fmaxf(l2, l3));
        float e0 = expf(l0 - mx), e1 = expf(l1 - mx), e2 = expf(l2 - mx), e3 = expf(l3 - mx);
        float inv = 1.f / (e0 + e1 + e2 + e3);
        sPL[b*4] = e0*inv; sPL[b*4+1] = e1*inv; sPL[b*4+2] = e2*inv; sPL[b*4+3] = e3*inv;
    }
    __syncthreads();

    // ---- feature = sum_m p_last[m] * x[m] -> sF0 ----
    for (int idx = tid; idx < TB*DD; idx += NT) {
        int b = idx >> 7, d = idx & 127;
        float v = sPL[b*4 + 0] * sX[0*XS + b*APAD + d]
                + sPL[b*4 + 1] * sX[1*XS + b*APAD + d]
                + sPL[b*4 + 2] * sX[2*XS + b*APAD + d]
                + sPL[b*4 + 3] * sX[3*XS + b*APAD + d];
        sF0[b*APAD + d] = v;
    }
    __syncthreads();

    // ---- a1 = relu(feature @ Wa1 + ba1) -> sG (G dead now) ----
    gemm_tile(Wa1, ba1, sF0, APAD, sG, APAD, sW, DD);

    // ---- adv = a1 @ Wa2 + ba2 ----
    for (int i = tid; i < 256; i += NT) ((float4*)sW)[i] = ((const float4*)Wa2)[i];
    __syncthreads();
    for (int idx = tid; idx < TB*8; idx += NT) {
        int b = idx >> 3, a = idx & 7;
        const float* arow = sG + b*APAD;
        float acc = ba2[a];
        #pragma unroll 8
        for (int k = 0; k < DD; ++k) acc = fmaf(arow[k], sW[k*8 + a], acc);
        sLog[b*8 + a] = acc;
    }
    __syncthreads();

    // ---- value + dueling combine + store ----
    if (tid < TB) {
        int b = tid;
        float advv[8];
        float s = 0.f;
        #pragma unroll
        for (int a = 0; a < 8; ++a) { advv[a] = sLog[b*8 + a]; s += advv[a]; }
        float mean = s * 0.125f;
        const float* frow = sF0 + b*APAD;
        float v = bv[0];
        #pragma unroll 8
        for (int k = 0; k < DD; ++k) v = fmaf(frow[k], Wv[k], v);
        float* orow = out + (size_t)(row0 + b)*8;
        #pragma unroll
        for (int a = 0; a < 8; ++a) orow[a] = advv[a] - mean + v;
    }
}

extern "C" void kernel_launch(void* const* d_in, const int* in_sizes, int n_in,
                              void* d_out, int out_size) {
    const float* o       = (const float*)d_in[0];
    const float* z_map   = (const float*)d_in[1];
    const float* cp      = (const float*)d_in[2];
    const float* Wb      = (const float*)d_in[3];
    const float* bb      = (const float*)d_in[4];
    const float* Wz      = (const float*)d_in[5];
    const float* bz      = (const float*)d_in[6];
    const float* Wm      = (const float*)d_in[7];
    const float* bm      = (const float*)d_in[8];
    const float* Wg      = (const float*)d_in[9];
    const float* Wg_last = (const float*)d_in[10];
    const float* Wv      = (const float*)d_in[11];
    const float* bv      = (const float*)d_in[12];
    const float* Wa1     = (const float*)d_in[13];
    const float* ba1     = (const float*)d_in[14];
    const float* Wa2     = (const float*)d_in[15];
    const float* ba2     = (const float*)d_in[16];
    float* out = (float*)d_out;

    const int Btot = in_sizes[0] / 256;
    const int grid = (Btot + TB - 1) / TB;

    cudaFuncSetAttribute((const void*)qnet_kernel,
                         cudaFuncAttributeMaxDynamicSharedMemorySize, SMEM_BYTES);

    qnet_kernel<<<grid, NT, SMEM_BYTES>>>(
        o, z_map, cp, Wb, bb, Wz, bz, Wm, bm, Wg, Wg_last,
        Wv, bv, Wa1, ba1, Wa2, ba2, out);
}